// round 14
// baseline (speedup 1.0000x reference)
#include <cuda_runtime.h>
#include <cuda_bf16.h>
#include <cstdint>

#define T_LEN 200
#define B_SZ  1024
#define D_SZ  128
#define G3    384
#define RB    8
#define SSTR  24    // state row stride (halfs): 48B, 16B-aligned, conflict-free

// Precomputed x-side: [T*B][384] = (xWau+bau | xWar+bar | xWac+bac)
__device__ float g_X[(size_t)T_LEN * B_SZ * G3];

// ---------- tensor-core helpers ----------
__device__ __forceinline__ void ldsm4(uint32_t* r, const void* p) {
    uint32_t a = (uint32_t)__cvta_generic_to_shared(p);
    asm volatile("ldmatrix.sync.aligned.m8n8.x4.shared.b16 {%0,%1,%2,%3}, [%4];"
                 : "=r"(r[0]), "=r"(r[1]), "=r"(r[2]), "=r"(r[3]) : "r"(a));
}
__device__ __forceinline__ void ldsm4t(uint32_t* r, const void* p) {
    uint32_t a = (uint32_t)__cvta_generic_to_shared(p);
    asm volatile("ldmatrix.sync.aligned.m8n8.x4.trans.shared.b16 {%0,%1,%2,%3}, [%4];"
                 : "=r"(r[0]), "=r"(r[1]), "=r"(r[2]), "=r"(r[3]) : "r"(a));
}
__device__ __forceinline__ void ldsm2t(uint32_t* r, const void* p) {
    uint32_t a = (uint32_t)__cvta_generic_to_shared(p);
    asm volatile("ldmatrix.sync.aligned.m8n8.x2.trans.shared.b16 {%0,%1}, [%2];"
                 : "=r"(r[0]), "=r"(r[1]) : "r"(a));
}
__device__ __forceinline__ void mma_bf16(float* c, const uint32_t* a,
                                         uint32_t b0, uint32_t b1) {
    asm volatile(
        "mma.sync.aligned.m16n8k16.row.col.f32.bf16.bf16.f32 "
        "{%0,%1,%2,%3}, {%4,%5,%6,%7}, {%8,%9}, {%0,%1,%2,%3};"
        : "+f"(c[0]), "+f"(c[1]), "+f"(c[2]), "+f"(c[3])
        : "r"(a[0]), "r"(a[1]), "r"(a[2]), "r"(a[3]), "r"(b0), "r"(b1));
}
__device__ __forceinline__ void bf16split(float v, __nv_bfloat16& h, __nv_bfloat16& l) {
    h = __float2bfloat16(v);
    l = __float2bfloat16(v - __bfloat162float(h));
}

// =====================================================================
// Kernel 1: X-side GEMM on tensor cores, bf16-split (UNCHANGED, validated).
// =====================================================================
#define GBM  64
#define GSTR 136

__global__ __launch_bounds__(256) void gemm_x_mma(
    const float* __restrict__ Xin,
    const float* __restrict__ Wau, const float* __restrict__ bau,
    const float* __restrict__ War, const float* __restrict__ bar,
    const float* __restrict__ Wac, const float* __restrict__ bac)
{
    extern __shared__ __nv_bfloat16 smg[];
    __nv_bfloat16* Ah = smg;
    __nv_bfloat16* Al = Ah + GBM * GSTR;
    __nv_bfloat16* Bh = Al + GBM * GSTR;
    __nv_bfloat16* Bl = Bh + 128 * GSTR;

    const int tid  = threadIdx.x;
    const int m0   = blockIdx.x * GBM;
    const int gate = blockIdx.y;
    const float* W    = (gate == 0) ? Wau : ((gate == 1) ? War : Wac);
    const float* bias = (gate == 0) ? bau : ((gate == 1) ? bar : bac);

    #pragma unroll
    for (int l = 0; l < 8; l++) {
        int idx = tid + l * 256;
        int row = idx >> 5;
        int c4  = idx & 31;
        float4 v = *(const float4*)(Xin + (size_t)(m0 + row) * D_SZ + c4 * 4);
        float vv[4] = {v.x, v.y, v.z, v.w};
        #pragma unroll
        for (int j = 0; j < 4; j++) {
            __nv_bfloat16 h, lo; bf16split(vv[j], h, lo);
            Ah[row * GSTR + c4 * 4 + j] = h;
            Al[row * GSTR + c4 * 4 + j] = lo;
        }
    }
    #pragma unroll
    for (int l = 0; l < 16; l++) {
        int idx = tid + l * 256;
        int row = idx >> 5;
        int c4  = idx & 31;
        float4 v = *(const float4*)(W + (size_t)row * D_SZ + c4 * 4);
        float vv[4] = {v.x, v.y, v.z, v.w};
        #pragma unroll
        for (int j = 0; j < 4; j++) {
            __nv_bfloat16 h, lo; bf16split(vv[j], h, lo);
            Bh[row * GSTR + c4 * 4 + j] = h;
            Bl[row * GSTR + c4 * 4 + j] = lo;
        }
    }
    __syncthreads();

    const int lane = tid & 31;
    const int wid  = tid >> 5;
    const int wm   = wid & 1;
    const int wn   = wid >> 1;

    float c[2][4][4];
    #pragma unroll
    for (int mt = 0; mt < 2; mt++)
        #pragma unroll
        for (int nt = 0; nt < 4; nt++)
            #pragma unroll
            for (int j = 0; j < 4; j++) c[mt][nt][j] = 0.0f;

    const int lr = lane & 15;
    const int lc = (lane >> 4) * 8;

    #pragma unroll
    for (int kc = 0; kc < 8; kc++) {
        uint32_t ah[2][4], al[2][4], bh[2][4], bl[2][4];
        #pragma unroll
        for (int mt = 0; mt < 2; mt++) {
            const __nv_bfloat16* pa =
                Ah + (wm * 32 + mt * 16 + lr) * GSTR + kc * 16 + lc;
            ldsm4(ah[mt], pa);
            ldsm4(al[mt], pa + (Al - Ah));
        }
        #pragma unroll
        for (int bt = 0; bt < 2; bt++) {
            const __nv_bfloat16* pb =
                Bh + (kc * 16 + lr) * GSTR + wn * 32 + bt * 16 + lc;
            ldsm4t(bh[bt], pb);
            ldsm4t(bl[bt], pb + (Bl - Bh));
        }
        #pragma unroll
        for (int mt = 0; mt < 2; mt++)
            #pragma unroll
            for (int bt = 0; bt < 2; bt++)
                #pragma unroll
                for (int h = 0; h < 2; h++) {
                    float* cc = c[mt][bt * 2 + h];
                    mma_bf16(cc, ah[mt], bh[bt][2 * h], bh[bt][2 * h + 1]);
                    mma_bf16(cc, ah[mt], bl[bt][2 * h], bl[bt][2 * h + 1]);
                    mma_bf16(cc, al[mt], bh[bt][2 * h], bh[bt][2 * h + 1]);
                }
    }

    const int mrow = lane >> 2;
    const int ncol = (lane & 3) * 2;
    #pragma unroll
    for (int mt = 0; mt < 2; mt++) {
        #pragma unroll
        for (int nt = 0; nt < 4; nt++) {
            int n = wn * 32 + nt * 8 + ncol;
            float b0 = __ldg(bias + n);
            float b1 = __ldg(bias + n + 1);
            int m = m0 + wm * 32 + mt * 16 + mrow;
            float* o0 = g_X + (size_t)m * G3 + gate * 128 + n;
            *(float2*)o0 = make_float2(c[mt][nt][0] + b0, c[mt][nt][1] + b1);
            float* o1 = g_X + (size_t)(m + 8) * G3 + gate * 128 + n;
            *(float2*)o1 = make_float2(c[mt][nt][2] + b0, c[mt][nt][3] + b1);
        }
    }
}

// =====================================================================
// Kernel 2: recurrence on tensor cores, HI-WEIGHTS HOISTED TO REGISTERS.
// 128 CTAs x 8 rows, 256 threads (8 warps).
// Wh fragments (3 gates x 8 kc x 4 regs = 96 regs/thread) loaded ONCE
// before the time loop; only Wl + state are ldsm'd per step.
// Crossbar/step: 1792 -> ~1024 cyc (Wl 96 + state 32 wavefronts x 8 warps).
// Everything else identical to the validated R13 kernel.
// =====================================================================
extern __shared__ __nv_bfloat16 smr[];

__global__ __launch_bounds__(256, 1) void augru_rec_mma(
    const float* __restrict__ state, const float* __restrict__ att,
    const float* __restrict__ mask,
    const float* __restrict__ Wbu, const float* __restrict__ Wbr,
    const float* __restrict__ Wbc,
    float* __restrict__ out)
{
    __nv_bfloat16* Wh = smr;                    // [384][128] swizzled
    __nv_bfloat16* Wl = Wh + G3 * 128;
    __nv_bfloat16* Sh = Wl + G3 * 128;          // [2][128][SSTR]
    __nv_bfloat16* Sl = Sh + 2 * 128 * SSTR;

    const int tid  = threadIdx.x;
    const int lane = tid & 31;
    const int w    = tid >> 5;
    const int b0   = blockIdx.x * RB;

    // ---- weights: transpose + bf16-split into swizzled smem ----
    #pragma unroll
    for (int g = 0; g < 3; g++) {
        const float* W = (g == 0) ? Wbu : ((g == 1) ? Wbr : Wbc);
        for (int i = tid; i < 128 * 64; i += 256) {
            int m  = i & 127;
            int k2 = (i >> 7) * 2;
            float v0 = W[(size_t)k2 * D_SZ + m];
            float v1 = W[(size_t)(k2 + 1) * D_SZ + m];
            __nv_bfloat16 h0, l0, h1, l1;
            bf16split(v0, h0, l0);
            bf16split(v1, h1, l1);
            int off = (g * 128 + m) * 128 + (((k2 >> 3) ^ (m & 7)) << 3) + (k2 & 7);
            __nv_bfloat162 ph; ph.x = h0; ph.y = h1;
            __nv_bfloat162 pl; pl.x = l0; pl.y = l1;
            *(__nv_bfloat162*)(Wh + off) = ph;
            *(__nv_bfloat162*)(Wl + off) = pl;
        }
    }

    // ---- lane ownership ----
    const int d0 = 16 * w + (lane >> 2);
    const int d1 = d0 + 8;
    const int n0 = (lane & 3) * 2;
    const int n1 = n0 + 1;

    float s_reg[4];
    s_reg[0] = state[(size_t)(b0 + n0) * D_SZ + d0];
    s_reg[1] = state[(size_t)(b0 + n1) * D_SZ + d0];
    s_reg[2] = state[(size_t)(b0 + n0) * D_SZ + d1];
    s_reg[3] = state[(size_t)(b0 + n1) * D_SZ + d1];

    {
        __nv_bfloat16 h0, l0, h1, l1;
        bf16split(s_reg[0], h0, l0); bf16split(s_reg[1], h1, l1);
        __nv_bfloat162 ph; ph.x = h0; ph.y = h1;
        __nv_bfloat162 pl; pl.x = l0; pl.y = l1;
        *(__nv_bfloat162*)(Sh + d0 * SSTR + n0) = ph;
        *(__nv_bfloat162*)(Sl + d0 * SSTR + n0) = pl;
        bf16split(s_reg[2], h0, l0); bf16split(s_reg[3], h1, l1);
        ph.x = h0; ph.y = h1; pl.x = l0; pl.y = l1;
        *(__nv_bfloat162*)(Sh + d1 * SSTR + n0) = ph;
        *(__nv_bfloat162*)(Sl + d1 * SSTR + n0) = pl;
    }
    __syncthreads();

    const int lr = lane & 15;

    // ---- HOIST: load all hi-weight fragments into registers (96 regs) ----
    uint32_t whr[3][8][4];
    #pragma unroll
    for (int kc = 0; kc < 8; kc++) {
        int chunk = ((kc * 2 + (lane >> 4)) ^ (lr & 7)) << 3;
        #pragma unroll
        for (int g = 0; g < 3; g++) {
            int mrow = g * 128 + 16 * w + lr;
            ldsm4(whr[g][kc], Wh + mrow * 128 + chunk);
        }
    }

    int cur = 0;
    for (int t = 0; t < T_LEN; t++) {
        // ---- prefetch x-side + att + mask ----
        const float* Xb = g_X + ((size_t)t * B_SZ + b0) * G3;
        float xu[4], xr[4], xc[4];
        xu[0] = Xb[n0 * G3 + d0];        xu[1] = Xb[n1 * G3 + d0];
        xu[2] = Xb[n0 * G3 + d1];        xu[3] = Xb[n1 * G3 + d1];
        xr[0] = Xb[n0 * G3 + 128 + d0];  xr[1] = Xb[n1 * G3 + 128 + d0];
        xr[2] = Xb[n0 * G3 + 128 + d1];  xr[3] = Xb[n1 * G3 + 128 + d1];
        xc[0] = Xb[n0 * G3 + 256 + d0];  xc[1] = Xb[n1 * G3 + 256 + d0];
        xc[2] = Xb[n0 * G3 + 256 + d1];  xc[3] = Xb[n1 * G3 + 256 + d1];
        float a0 = __ldg(att + (size_t)t * B_SZ + b0 + n0);
        float a1 = __ldg(att + (size_t)t * B_SZ + b0 + n1);
        float k0 = __ldg(mask + (size_t)(b0 + n0) * T_LEN + t);
        float k1 = __ldg(mask + (size_t)(b0 + n1) * T_LEN + t);

        float acc[3][4];
        #pragma unroll
        for (int g = 0; g < 3; g++)
            #pragma unroll
            for (int j = 0; j < 4; j++) acc[g][j] = 0.0f;

        const __nv_bfloat16* Sbh = Sh + cur * 128 * SSTR;
        const __nv_bfloat16* Sbl = Sl + cur * 128 * SSTR;

        #pragma unroll
        for (int kc = 0; kc < 8; kc++) {
            uint32_t bh[2], bl[2];
            ldsm2t(bh, Sbh + (kc * 16 + lr) * SSTR);
            ldsm2t(bl, Sbl + (kc * 16 + lr) * SSTR);
            int chunk = ((kc * 2 + (lane >> 4)) ^ (lr & 7)) << 3;
            #pragma unroll
            for (int g = 0; g < 3; g++) {
                int mrow = g * 128 + 16 * w + lr;
                uint32_t al[4];
                ldsm4(al, Wl + mrow * 128 + chunk);
                mma_bf16(acc[g], whr[g][kc], bh[0], bh[1]);
                mma_bf16(acc[g], whr[g][kc], bl[0], bl[1]);
                mma_bf16(acc[g], al, bh[0], bh[1]);
            }
        }

        // ---- gates + state update (lane-local) ----
        float sn[4];
        #pragma unroll
        for (int j = 0; j < 4; j++) {
            float hu = acc[0][j] + xu[j];
            float hr = acc[1][j] + xr[j];
            float dc = acc[2][j];
            float ug = __fdividef(1.0f, 1.0f + __expf(-hu));
            float rg = __fdividef(1.0f, 1.0f + __expf(-hr));
            float hc = xc[j] + rg * dc;
            float e2 = __expf(2.0f * hc);
            float cd = 1.0f - __fdividef(2.0f, e2 + 1.0f);   // tanh
            float av = (j & 1) ? a1 : a0;
            float mk = (j & 1) ? k1 : k0;
            sn[j] = s_reg[j] + mk * av * ug * (cd - s_reg[j]);
            s_reg[j] = sn[j];
        }

        // ---- write next state buffer ----
        const int nxt = cur ^ 1;
        __nv_bfloat16* Dh = Sh + nxt * 128 * SSTR;
        __nv_bfloat16* Dl = Sl + nxt * 128 * SSTR;
        {
            __nv_bfloat16 h0, l0, h1, l1;
            bf16split(sn[0], h0, l0); bf16split(sn[1], h1, l1);
            __nv_bfloat162 ph; ph.x = h0; ph.y = h1;
            __nv_bfloat162 pl; pl.x = l0; pl.y = l1;
            *(__nv_bfloat162*)(Dh + d0 * SSTR + n0) = ph;
            *(__nv_bfloat162*)(Dl + d0 * SSTR + n0) = pl;
            bf16split(sn[2], h0, l0); bf16split(sn[3], h1, l1);
            ph.x = h0; ph.y = h1; pl.x = l0; pl.y = l1;
            *(__nv_bfloat162*)(Dh + d1 * SSTR + n0) = ph;
            *(__nv_bfloat162*)(Dl + d1 * SSTR + n0) = pl;
        }
        __syncthreads();
        cur = nxt;
    }

    out[(size_t)(b0 + n0) * D_SZ + d0] = s_reg[0];
    out[(size_t)(b0 + n1) * D_SZ + d0] = s_reg[1];
    out[(size_t)(b0 + n0) * D_SZ + d1] = s_reg[2];
    out[(size_t)(b0 + n1) * D_SZ + d1] = s_reg[3];
}

// =====================================================================
extern "C" void kernel_launch(void* const* d_in, const int* in_sizes, int n_in,
                              void* d_out, int out_size)
{
    const float* inputs = (const float*)d_in[0];
    const float* state  = (const float*)d_in[1];
    const float* att    = (const float*)d_in[2];
    const float* mask   = (const float*)d_in[3];
    int w = (n_in >= 14) ? 5 : 4;
    const float* Wau = (const float*)d_in[w + 0];
    const float* bau = (const float*)d_in[w + 1];
    const float* Wbu = (const float*)d_in[w + 2];
    const float* War = (const float*)d_in[w + 3];
    const float* bar = (const float*)d_in[w + 4];
    const float* Wbr = (const float*)d_in[w + 5];
    const float* Wac = (const float*)d_in[w + 6];
    const float* bac = (const float*)d_in[w + 7];
    const float* Wbc = (const float*)d_in[w + 8];
    float* out = (float*)d_out;
    (void)in_sizes; (void)out_size;

    // Tensor-core x-side GEMM: grid (3200, 3)
    size_t gsm = (size_t)(2 * GBM * GSTR + 2 * 128 * GSTR) * sizeof(__nv_bfloat16);
    cudaFuncSetAttribute(gemm_x_mma, cudaFuncAttributeMaxDynamicSharedMemorySize,
                         (int)gsm);
    dim3 g1(T_LEN * B_SZ / GBM, 3);
    gemm_x_mma<<<g1, 256, gsm>>>(inputs, Wau, bau, War, bar, Wac, bac);

    // Tensor-core recurrence: smem = 221,184 B
    size_t rsm = (size_t)(2 * G3 * 128 + 4 * 128 * SSTR) * sizeof(__nv_bfloat16);
    cudaFuncSetAttribute(augru_rec_mma, cudaFuncAttributeMaxDynamicSharedMemorySize,
                         (int)rsm);
    augru_rec_mma<<<B_SZ / RB, 256, rsm>>>(state, att, mask, Wbu, Wbr, Wbc, out);
}